// round 6
// baseline (speedup 1.0000x reference)
#include <cuda_runtime.h>
#include <cuda_bf16.h>
#include <cstdint>

// ---------------- problem constants ----------------
#define BB 4096
#define VV 20
#define DD 768
#define MROWS (BB * VV)        // 81920
#define NN (2 * DD)            // 1536 interleaved (m1,m2)
#define KK DD                  // 768

// ---------------- scratch (static device globals; no allocations) ----------------
__device__ __nv_bfloat16 g_Xn[(size_t)MROWS * DD];   // softmaxed A, bf16 (126 MB)
__device__ __nv_bfloat16 g_Wc[(size_t)NN * DD];      // interleaved weights bf16 (2.4 MB)

// ---------------- baseline-PTX helpers ----------------
__device__ __forceinline__ uint32_t smem_u32(const void* p) {
    uint32_t a;
    asm("{ .reg .u64 t; cvta.to.shared.u64 t, %1; cvt.u32.u64 %0, t; }" : "=r"(a) : "l"(p));
    return a;
}
__device__ __forceinline__ void cp_async16(uint32_t saddr, const void* gptr) {
    asm volatile("cp.async.cg.shared.global [%0], [%1], 16;\n" :: "r"(saddr), "l"(gptr));
}
#define CP_COMMIT() asm volatile("cp.async.commit_group;\n" ::: "memory")
#define CP_WAIT_1() asm volatile("cp.async.wait_group 1;\n" ::: "memory")
#define CP_WAIT_0() asm volatile("cp.async.wait_group 0;\n" ::: "memory")

__device__ __forceinline__ void ldsm_x4(uint32_t& r0, uint32_t& r1, uint32_t& r2, uint32_t& r3,
                                        uint32_t addr) {
    asm volatile("ldmatrix.sync.aligned.m8n8.x4.shared.b16 {%0,%1,%2,%3}, [%4];"
                 : "=r"(r0), "=r"(r1), "=r"(r2), "=r"(r3) : "r"(addr));
}
__device__ __forceinline__ void ldsm_x2(uint32_t& r0, uint32_t& r1, uint32_t addr) {
    asm volatile("ldmatrix.sync.aligned.m8n8.x2.shared.b16 {%0,%1}, [%2];"
                 : "=r"(r0), "=r"(r1) : "r"(addr));
}
__device__ __forceinline__ void mma16816(float* c, const uint32_t* a, uint32_t b0, uint32_t b1) {
    asm volatile(
        "mma.sync.aligned.m16n8k16.row.col.f32.bf16.bf16.f32 "
        "{%0,%1,%2,%3}, {%4,%5,%6,%7}, {%8,%9}, {%0,%1,%2,%3};"
        : "+f"(c[0]), "+f"(c[1]), "+f"(c[2]), "+f"(c[3])
        : "r"(a[0]), "r"(a[1]), "r"(a[2]), "r"(a[3]), "r"(b0), "r"(b1));
}

// ---------------- kernel 1: interleave + cast weights ----------------
__global__ void prep_w(const float* __restrict__ W1, const float* __restrict__ W2) {
    int idx = blockIdx.x * blockDim.x + threadIdx.x;
    if (idx >= NN * DD) return;
    int n = idx / DD, k = idx - n * DD;
    int e = n >> 1;
    float v = (n & 1) ? W2[e * DD + k] : W1[e * DD + k];
    g_Wc[idx] = __float2bfloat16(v);
}

// ---------------- kernel 2: row softmax -> bf16 ----------------
__global__ void __launch_bounds__(256) softmax_rows(const float* __restrict__ vf) {
    int row = blockIdx.x;
    int tid = threadIdx.x;
    const float* x = vf + (size_t)row * DD;
    float a = x[tid], b = x[tid + 256], c = x[tid + 512];
    float m = fmaxf(a, fmaxf(b, c));
    #pragma unroll
    for (int o = 16; o; o >>= 1) m = fmaxf(m, __shfl_xor_sync(0xffffffffu, m, o));
    __shared__ float red[8];
    __shared__ float bc_max, bc_inv;
    int w = tid >> 5;
    if ((tid & 31) == 0) red[w] = m;
    __syncthreads();
    if (tid == 0) {
        float t = red[0];
        #pragma unroll
        for (int i = 1; i < 8; i++) t = fmaxf(t, red[i]);
        bc_max = t;
    }
    __syncthreads();
    float M_ = bc_max;
    float e0 = __expf(a - M_), e1 = __expf(b - M_), e2 = __expf(c - M_);
    float s = e0 + e1 + e2;
    #pragma unroll
    for (int o = 16; o; o >>= 1) s += __shfl_xor_sync(0xffffffffu, s, o);
    __syncthreads();
    if ((tid & 31) == 0) red[w] = s;
    __syncthreads();
    if (tid == 0) {
        float t = 0.f;
        #pragma unroll
        for (int i = 0; i < 8; i++) t += red[i];
        bc_inv = 1.f / t;
    }
    __syncthreads();
    float inv = bc_inv;
    __nv_bfloat16* dst = g_Xn + (size_t)row * DD;
    dst[tid]       = __float2bfloat16(e0 * inv);
    dst[tid + 256] = __float2bfloat16(e1 * inv);
    dst[tid + 512] = __float2bfloat16(e2 * inv);
}

// ---------------- kernel 3: HMMA GEMM (reg-pipelined) + fully fused epilogue ----------------
// Block: e-span [E0, E0+64), n tile covers halo [E0-2, E0+66) => 136 cols pad to 144.
#define TM 128
#define TNB 144
#define KC 64
#define NKC (KK / KC)                      // 12
#define A_BYTES (TM * 128)                 // 16384
#define B_BYTES (TNB * 128)                // 18432
#define STAGE_BYTES (A_BYTES + B_BYTES)    // 34816
#define NSTAGE 4
#define SM_TOTAL (NSTAGE * STAGE_BYTES)    // 139264
// epilogue planes alias stages 0/1 (bytes [0, 69632)); last chunk (c=11) uses slot 3
#define SF_STRIDE 69                       // fused plane [128][68]
#define SC_STRIDE 67                       // conv1 plane [128][66]

__device__ __forceinline__ uint32_t sw128(uint32_t off) {
    return off ^ ((off >> 3) & 0x70);
}

__device__ __forceinline__ void load_stage(uint32_t sbase, int slot, int kc, int tid,
                                           const __nv_bfloat16* Ab, int n_begin) {
    uint32_t abase = sbase + slot * STAGE_BYTES;
    uint32_t bbase = abase + A_BYTES;
    #pragma unroll
    for (int t = 0; t < 4; t++) {
        int idx = tid + t * 256;
        int r = idx >> 3, i = idx & 7;
        uint32_t off = (uint32_t)(r * 128 + i * 16);
        cp_async16(abase + sw128(off), (const char*)(Ab + (size_t)r * DD + kc * KC) + i * 16);
    }
    #pragma unroll
    for (int t = 0; t < 5; t++) {
        int idx = tid + t * 256;
        if (idx < TNB * 8) {
            int r = idx >> 3, i = idx & 7;
            int ng = n_begin + r;
            ng = ng < 0 ? 0 : (ng >= NN ? NN - 1 : ng);
            uint32_t off = (uint32_t)(r * 128 + i * 16);
            cp_async16(bbase + sw128(off),
                       (const char*)(g_Wc + (size_t)ng * DD + kc * KC) + i * 16);
        }
    }
    CP_COMMIT();
}

struct Frag {
    uint32_t A[2][4];
    uint32_t B[9][2];
};

__device__ __forceinline__ void frag_load(Frag& f, uint32_t abase, uint32_t bbase, int ks,
                                          uint32_t a_row_off, uint32_t b_row_base,
                                          uint32_t b_x2_off) {
    #pragma unroll
    for (int mf = 0; mf < 2; mf++)
        ldsm_x4(f.A[mf][0], f.A[mf][1], f.A[mf][2], f.A[mf][3],
                abase + sw128(a_row_off + mf * 16 * 128 + ks * 32));
    #pragma unroll
    for (int nf2 = 0; nf2 < 4; nf2++) {
        uint32_t r0, r1, r2, r3;
        ldsm_x4(r0, r1, r2, r3, bbase + sw128(b_row_base + nf2 * 16 * 128 + ks * 32));
        f.B[nf2 * 2][0] = r0;     f.B[nf2 * 2][1] = r1;
        f.B[nf2 * 2 + 1][0] = r2; f.B[nf2 * 2 + 1][1] = r3;
    }
    ldsm_x2(f.B[8][0], f.B[8][1], bbase + sw128(b_x2_off + ks * 32));
}

__device__ __forceinline__ void frag_mma(float acc[2][9][4], const Frag& f) {
    #pragma unroll
    for (int nf = 0; nf < 9; nf++) {
        mma16816(acc[0][nf], f.A[0], f.B[nf][0], f.B[nf][1]);
        mma16816(acc[1][nf], f.A[1], f.B[nf][0], f.B[nf][1]);
    }
}

__global__ void __launch_bounds__(256, 1) gemm_fused_kernel(const float* __restrict__ text,
                                                            const float* __restrict__ b1,
                                                            const float* __restrict__ b2,
                                                            const float* __restrict__ cw1,
                                                            const float* __restrict__ cb1,
                                                            const float* __restrict__ cw2,
                                                            const float* __restrict__ cb2,
                                                            float* __restrict__ out) {
    extern __shared__ char smem[];
    uint32_t sbase = smem_u32(smem);
    int tid = threadIdx.x, wid = tid >> 5, lane = tid & 31;
    int mw = wid & 3, nw = wid >> 2;           // warp grid 4(m) x 2(n), warp tile 32x72
    int E0 = blockIdx.x * 64;
    int m0 = blockIdx.y * TM;
    int n_begin = 2 * E0 - 4;

    const __nv_bfloat16* Ab = g_Xn + (size_t)m0 * DD;

    float acc[2][9][4];
    #pragma unroll
    for (int i = 0; i < 2; i++)
        #pragma unroll
        for (int j = 0; j < 9; j++)
            #pragma unroll
            for (int q = 0; q < 4; q++) acc[i][j][q] = 0.f;

    const uint32_t a_row_off = (uint32_t)((mw * 32 + (lane & 15)) * 128 + ((lane >> 4) * 16));
    const uint32_t b_row_base = (uint32_t)((nw * 72 + (lane & 7) + (((lane >> 4) & 1) << 3)) * 128
                                           + (((lane >> 3) & 1) * 16));
    const uint32_t b_x2_off = (uint32_t)((nw * 72 + 64 + (lane & 7)) * 128
                                         + (((lane >> 3) & 1) * 16));

    // prologue: chunks 0,1 staged; chunk0 fragments preloaded into buf0
    load_stage(sbase, 0, 0, tid, Ab, n_begin);
    load_stage(sbase, 1, 1, tid, Ab, n_begin);
    CP_WAIT_1();
    __syncthreads();

    Frag frag[2];
    frag_load(frag[0], sbase, sbase + A_BYTES, 0, a_row_off, b_row_base, b_x2_off);

    // mainloop: buf parity == ks parity (4 ks per chunk)
    #pragma unroll 4
    for (int c = 0; c < NKC; c++) {
        if (c + 2 < NKC)
            load_stage(sbase, (c + 2) & 3, c + 2, tid, Ab, n_begin);
        uint32_t abase = sbase + (c & 3) * STAGE_BYTES;
        uint32_t bbase = abase + A_BYTES;
        #pragma unroll
        for (int ks = 0; ks < 4; ks++) {
            int cur = ks & 1;
            if (ks < 3) {
                frag_load(frag[cur ^ 1], abase, bbase, ks + 1,
                          a_row_off, b_row_base, b_x2_off);
            } else if (c + 1 < NKC) {
                // stage boundary: chunk c+1 guaranteed resident, then prefetch its ks0
                if (c + 2 < NKC) CP_WAIT_1(); else CP_WAIT_0();
                __syncthreads();
                uint32_t nab = sbase + ((c + 1) & 3) * STAGE_BYTES;
                frag_load(frag[cur ^ 1], nab, nab + A_BYTES, 0,
                          a_row_off, b_row_base, b_x2_off);
            }
            frag_mma(acc, frag[cur]);
        }
    }

    // ---- epilogue phase 1: relu(text*(m1+b1) + (m2+b2)) -> SF ----
    float* SF = (float*)smem;                  // [128][SF_STRIDE], e_local in [0,68)
    float* SC = SF + 128 * SF_STRIDE;          // [128][SC_STRIDE], j in [0,66)
    __syncthreads();                           // all warps done with stage smem
    #pragma unroll
    for (int mf = 0; mf < 2; mf++) {
        int ml_a = mw * 32 + mf * 16 + (lane >> 2);
        int ml_b = ml_a + 8;
        int m_a = m0 + ml_a, m_b = m0 + ml_b;
        const float* trow_a = text + (size_t)(m_a / VV) * DD;
        const float* trow_b = text + (size_t)(m_b / VV) * DD;
        #pragma unroll
        for (int nf = 0; nf < 9; nf++) {
            int e_local = nw * 36 + nf * 4 + (lane & 3);
            if (e_local < 68) {
                int e_g = E0 - 2 + e_local;
                float va = 0.f, vb = 0.f;
                if (e_g >= 0 && e_g < DD) {
                    float bb1 = __ldg(b1 + e_g), bb2 = __ldg(b2 + e_g);
                    va = fmaxf(fmaf(__ldg(trow_a + e_g), acc[mf][nf][0] + bb1,
                                    acc[mf][nf][1] + bb2), 0.f);
                    vb = fmaxf(fmaf(__ldg(trow_b + e_g), acc[mf][nf][2] + bb1,
                                    acc[mf][nf][3] + bb2), 0.f);
                }
                SF[ml_a * SF_STRIDE + e_local] = va;
                SF[ml_b * SF_STRIDE + e_local] = vb;
            }
        }
    }
    __syncthreads();

    // ---- epilogue phase 2: conv1 + relu -> SC ----
    float w10 = __ldg(cw1), w11 = __ldg(cw1 + 1), w12 = __ldg(cw1 + 2), bc1 = __ldg(cb1);
    for (int idx = tid; idx < 128 * 66; idx += 256) {
        int ml = idx / 66, j = idx - ml * 66;
        int e_g = E0 - 1 + j;
        const float* F = SF + ml * SF_STRIDE + j;
        float v = fmaxf(w10 * F[0] + w11 * F[1] + w12 * F[2] + bc1, 0.f);
        SC[ml * SC_STRIDE + j] = (e_g >= 0 && e_g < DD) ? v : 0.f;
    }
    __syncthreads();

    // ---- epilogue phase 3: conv2 -> out ----
    float w20 = __ldg(cw2), w21 = __ldg(cw2 + 1), w22 = __ldg(cw2 + 2), bc2 = __ldg(cb2);
    for (int idx = tid; idx < 128 * 64; idx += 256) {
        int ml = idx >> 6, i = idx & 63;
        const float* C = SC + ml * SC_STRIDE + i;
        out[(size_t)(m0 + ml) * DD + E0 + i] = w20 * C[0] + w21 * C[1] + w22 * C[2] + bc2;
    }
}

// ---------------- launch ----------------
extern "C" void kernel_launch(void* const* d_in, const int* in_sizes, int n_in,
                              void* d_out, int out_size) {
    const float* text = (const float*)d_in[0];
    const float* vf   = (const float*)d_in[1];
    const float* W1   = (const float*)d_in[2];
    const float* b1   = (const float*)d_in[3];
    const float* W2   = (const float*)d_in[4];
    const float* b2   = (const float*)d_in[5];
    const float* cw1  = (const float*)d_in[6];
    const float* cb1  = (const float*)d_in[7];
    const float* cw2  = (const float*)d_in[8];
    const float* cb2  = (const float*)d_in[9];
    float* out = (float*)d_out;

    cudaFuncSetAttribute(gemm_fused_kernel, cudaFuncAttributeMaxDynamicSharedMemorySize, SM_TOTAL);

    prep_w<<<(NN * DD + 255) / 256, 256>>>(W1, W2);
    softmax_rows<<<MROWS, 256>>>(vf);
    gemm_fused_kernel<<<dim3(DD / 64, MROWS / TM), 256, SM_TOTAL>>>(
        text, b1, b2, cw1, cb1, cw2, cb2, out);
}

// round 9
// speedup vs baseline: 1.0028x; 1.0028x over previous
#include <cuda_runtime.h>
#include <cuda_fp16.h>
#include <cstdint>

// ---------------- problem constants ----------------
#define BB 4096
#define VV 20
#define DD 768
#define MROWS (BB * VV)        // 81920
#define NN (2 * DD)            // 1536 interleaved (m1,m2)
#define KK DD                  // 768

// ---------------- scratch (static device globals; no allocations) ----------------
__device__ __half g_Xn[(size_t)MROWS * DD];    // softmaxed A, fp16 (126 MB)
__device__ __half g_Wc[(size_t)NN * DD];       // interleaved weights fp16 (2.4 MB)
__device__ __half g_Fused[(size_t)MROWS * DD]; // relu(text*m1+m2), fp16 (126 MB)

// ---------------- baseline-PTX helpers ----------------
__device__ __forceinline__ uint32_t smem_u32(const void* p) {
    uint32_t a;
    asm("{ .reg .u64 t; cvta.to.shared.u64 t, %1; cvt.u32.u64 %0, t; }" : "=r"(a) : "l"(p));
    return a;
}
__device__ __forceinline__ void cp_async16(uint32_t saddr, const void* gptr) {
    asm volatile("cp.async.cg.shared.global [%0], [%1], 16;\n" :: "r"(saddr), "l"(gptr));
}
#define CP_COMMIT() asm volatile("cp.async.commit_group;\n" ::: "memory")
#define CP_WAIT_1() asm volatile("cp.async.wait_group 1;\n" ::: "memory")
#define CP_WAIT_0() asm volatile("cp.async.wait_group 0;\n" ::: "memory")

__device__ __forceinline__ void ldsm_x4(uint32_t& r0, uint32_t& r1, uint32_t& r2, uint32_t& r3,
                                        uint32_t addr) {
    asm volatile("ldmatrix.sync.aligned.m8n8.x4.shared.b16 {%0,%1,%2,%3}, [%4];"
                 : "=r"(r0), "=r"(r1), "=r"(r2), "=r"(r3) : "r"(addr));
}
__device__ __forceinline__ void mma16816(float* c, const uint32_t* a, uint32_t b0, uint32_t b1) {
    asm volatile(
        "mma.sync.aligned.m16n8k16.row.col.f32.f16.f16.f32 "
        "{%0,%1,%2,%3}, {%4,%5,%6,%7}, {%8,%9}, {%0,%1,%2,%3};"
        : "+f"(c[0]), "+f"(c[1]), "+f"(c[2]), "+f"(c[3])
        : "r"(a[0]), "r"(a[1]), "r"(a[2]), "r"(a[3]), "r"(b0), "r"(b1));
}

// ---------------- kernel 1: interleave + cast weights ----------------
__global__ void prep_w(const float* __restrict__ W1, const float* __restrict__ W2) {
    int idx = blockIdx.x * blockDim.x + threadIdx.x;
    if (idx >= NN * DD) return;
    int n = idx / DD, k = idx - n * DD;
    int e = n >> 1;
    float v = (n & 1) ? W2[e * DD + k] : W1[e * DD + k];
    g_Wc[idx] = __float2half_rn(v);
}

// ---------------- kernel 2: row softmax -> fp16 ----------------
__global__ void __launch_bounds__(256) softmax_rows(const float* __restrict__ vf) {
    int row = blockIdx.x;
    int tid = threadIdx.x;
    const float* x = vf + (size_t)row * DD;
    float a = x[tid], b = x[tid + 256], c = x[tid + 512];
    float m = fmaxf(a, fmaxf(b, c));
    #pragma unroll
    for (int o = 16; o; o >>= 1) m = fmaxf(m, __shfl_xor_sync(0xffffffffu, m, o));
    __shared__ float red[8];
    __shared__ float bc_max, bc_inv;
    int w = tid >> 5;
    if ((tid & 31) == 0) red[w] = m;
    __syncthreads();
    if (tid == 0) {
        float t = red[0];
        #pragma unroll
        for (int i = 1; i < 8; i++) t = fmaxf(t, red[i]);
        bc_max = t;
    }
    __syncthreads();
    float M_ = bc_max;
    float e0 = __expf(a - M_), e1 = __expf(b - M_), e2 = __expf(c - M_);
    float s = e0 + e1 + e2;
    #pragma unroll
    for (int o = 16; o; o >>= 1) s += __shfl_xor_sync(0xffffffffu, s, o);
    __syncthreads();
    if ((tid & 31) == 0) red[w] = s;
    __syncthreads();
    if (tid == 0) {
        float t = 0.f;
        #pragma unroll
        for (int i = 0; i < 8; i++) t += red[i];
        bc_inv = 1.f / t;
    }
    __syncthreads();
    float inv = bc_inv;
    __half* dst = g_Xn + (size_t)row * DD;
    dst[tid]       = __float2half_rn(e0 * inv);
    dst[tid + 256] = __float2half_rn(e1 * inv);
    dst[tid + 512] = __float2half_rn(e2 * inv);
}

// ---------------- kernel 3: fp16 HMMA GEMM + fused bias/relu epilogue ----------------
#define TM 128
#define TN 128
#define KC 64                              // 64 fp16 = 128B row
#define NKC (KK / KC)                      // 12
#define A_BYTES (TM * 128)                 // 16384
#define B_BYTES (TN * 128)                 // 16384
#define STAGE_BYTES (A_BYTES + B_BYTES)    // 32768
#define NSTAGE 3
#define SM_TOTAL (NSTAGE * STAGE_BYTES)    // 98304

__device__ __forceinline__ uint32_t sw128(uint32_t off) {
    return off ^ ((off >> 3) & 0x70);
}

__device__ __forceinline__ void load_stage(uint32_t sbase, int slot, int kc, int tid,
                                           const __half* Ab, const __half* Bw) {
    uint32_t abase = sbase + slot * STAGE_BYTES;
    uint32_t bbase = abase + A_BYTES;
    #pragma unroll
    for (int t = 0; t < 4; t++) {
        int idx = tid + t * 256;
        int r = idx >> 3, i = idx & 7;
        uint32_t off = (uint32_t)(r * 128 + i * 16);
        cp_async16(abase + sw128(off), (const char*)(Ab + (size_t)r * DD + kc * KC) + i * 16);
    }
    #pragma unroll
    for (int t = 0; t < 4; t++) {
        int idx = tid + t * 256;
        int r = idx >> 3, i = idx & 7;
        uint32_t off = (uint32_t)(r * 128 + i * 16);
        cp_async16(bbase + sw128(off), (const char*)(Bw + (size_t)r * DD + kc * KC) + i * 16);
    }
    CP_COMMIT();
}

__global__ void __launch_bounds__(256) gemm_kernel(const float* __restrict__ text,
                                                   const float* __restrict__ b1,
                                                   const float* __restrict__ b2) {
    extern __shared__ char smem[];
    uint32_t sbase = smem_u32(smem);
    int tid = threadIdx.x, wid = tid >> 5, lane = tid & 31;
    int mw = wid & 3, nw = wid >> 2;           // warp grid 4(m) x 2(n), warp tile 32x64
    int n0 = blockIdx.x * TN;
    int m0 = blockIdx.y * TM;

    const __half* Ab = g_Xn + (size_t)m0 * DD;
    const __half* Bw = g_Wc + (size_t)n0 * DD;

    float acc[2][8][4];
    #pragma unroll
    for (int i = 0; i < 2; i++)
        #pragma unroll
        for (int j = 0; j < 8; j++)
            #pragma unroll
            for (int q = 0; q < 4; q++) acc[i][j][q] = 0.f;

    // prologue: chunks 0,1 into slots 0,1
    load_stage(sbase, 0, 0, tid, Ab, Bw);
    load_stage(sbase, 1, 1, tid, Ab, Bw);

    const uint32_t a_row_off = (uint32_t)((mw * 32 + (lane & 15)) * 128 + ((lane >> 4) * 16));
    const uint32_t b_row_base = (uint32_t)((nw * 64 + (lane & 7) + (((lane >> 4) & 1) << 3)) * 128
                                           + (((lane >> 3) & 1) * 16));

    for (int c = 0; c < NKC; c++) {
        // chunk c complete when <=1 groups (c+1 in flight; c+2 not yet committed)
        if (c + 2 < NKC) CP_WAIT_1(); else CP_WAIT_0();
        __syncthreads();                       // single barrier per chunk (3-stage)
        if (c + 2 < NKC)
            load_stage(sbase, (c + 2) % NSTAGE, c + 2, tid, Ab, Bw);

        uint32_t abase = sbase + (c % NSTAGE) * STAGE_BYTES;
        uint32_t bbase = abase + A_BYTES;
        #pragma unroll
        for (int ks = 0; ks < 4; ks++) {
            uint32_t a[2][4];
            #pragma unroll
            for (int mf = 0; mf < 2; mf++)
                ldsm_x4(a[mf][0], a[mf][1], a[mf][2], a[mf][3],
                        abase + sw128(a_row_off + mf * 16 * 128 + ks * 32));
            #pragma unroll
            for (int nf2 = 0; nf2 < 4; nf2++) {
                uint32_t r0, r1, r2, r3;
                ldsm_x4(r0, r1, r2, r3,
                        bbase + sw128(b_row_base + nf2 * 16 * 128 + ks * 32));
                mma16816(acc[0][nf2 * 2],     a[0], r0, r1);
                mma16816(acc[0][nf2 * 2 + 1], a[0], r2, r3);
                mma16816(acc[1][nf2 * 2],     a[1], r0, r1);
                mma16816(acc[1][nf2 * 2 + 1], a[1], r2, r3);
            }
        }
    }

    // fused epilogue: relu(text*(m1+b1) + (m2+b2)) -> g_Fused (fp16)
    #pragma unroll
    for (int mf = 0; mf < 2; mf++) {
        int m_a = m0 + mw * 32 + mf * 16 + (lane >> 2);
        int m_b = m_a + 8;
        const float* trow_a = text + (size_t)(m_a / VV) * DD;
        const float* trow_b = text + (size_t)(m_b / VV) * DD;
        #pragma unroll
        for (int nf = 0; nf < 8; nf++) {
            int e = ((n0 + nw * 64 + nf * 8) >> 1) + (lane & 3);
            float bb1 = __ldg(b1 + e), bb2 = __ldg(b2 + e);
            float va = fmaxf(fmaf(__ldg(trow_a + e), acc[mf][nf][0] + bb1,
                                  acc[mf][nf][1] + bb2), 0.f);
            float vb = fmaxf(fmaf(__ldg(trow_b + e), acc[mf][nf][2] + bb1,
                                  acc[mf][nf][3] + bb2), 0.f);
            g_Fused[(size_t)m_a * DD + e] = __float2half_rn(va);
            g_Fused[(size_t)m_b * DD + e] = __float2half_rn(vb);
        }
    }
}

// ---------------- kernel 4: conv3 -> relu -> conv3, per row ----------------
__global__ void __launch_bounds__(256) conv_kernel(const float* __restrict__ cw1,
                                                   const float* __restrict__ cb1,
                                                   const float* __restrict__ cw2,
                                                   const float* __restrict__ cb2,
                                                   float* __restrict__ out) {
    __shared__ float s1[DD];
    __shared__ float s2[DD];
    int row = blockIdx.x, tid = threadIdx.x;
    const __half* src = g_Fused + (size_t)row * DD;
    float w10 = __ldg(cw1), w11 = __ldg(cw1 + 1), w12 = __ldg(cw1 + 2), bb1 = __ldg(cb1);
    float w20 = __ldg(cw2), w21 = __ldg(cw2 + 1), w22 = __ldg(cw2 + 2), bb2 = __ldg(cb2);
    s1[tid]       = __half2float(src[tid]);
    s1[tid + 256] = __half2float(src[tid + 256]);
    s1[tid + 512] = __half2float(src[tid + 512]);
    __syncthreads();
    #pragma unroll
    for (int t = 0; t < 3; t++) {
        int i = tid + t * 256;
        float l = (i > 0)      ? s1[i - 1] : 0.f;
        float r = (i < DD - 1) ? s1[i + 1] : 0.f;
        s2[i] = fmaxf(w10 * l + w11 * s1[i] + w12 * r + bb1, 0.f);
    }
    __syncthreads();
    float* dst = out + (size_t)row * DD;
    #pragma unroll
    for (int t = 0; t < 3; t++) {
        int i = tid + t * 256;
        float l = (i > 0)      ? s2[i - 1] : 0.f;
        float r = (i < DD - 1) ? s2[i + 1] : 0.f;
        dst[i] = w20 * l + w21 * s2[i] + w22 * r + bb2;
    }
}

// ---------------- launch (single stream) ----------------
extern "C" void kernel_launch(void* const* d_in, const int* in_sizes, int n_in,
                              void* d_out, int out_size) {
    const float* text = (const float*)d_in[0];
    const float* vf   = (const float*)d_in[1];
    const float* W1   = (const float*)d_in[2];
    const float* b1   = (const float*)d_in[3];
    const float* W2   = (const float*)d_in[4];
    const float* b2   = (const float*)d_in[5];
    const float* cw1  = (const float*)d_in[6];
    const float* cb1  = (const float*)d_in[7];
    const float* cw2  = (const float*)d_in[8];
    const float* cb2  = (const float*)d_in[9];
    float* out = (float*)d_out;

    cudaFuncSetAttribute(gemm_kernel, cudaFuncAttributeMaxDynamicSharedMemorySize, SM_TOTAL);

    prep_w<<<(NN * DD + 255) / 256, 256>>>(W1, W2);
    softmax_rows<<<MROWS, 256>>>(vf);
    gemm_kernel<<<dim3(NN / TN, MROWS / TM), 256, SM_TOTAL>>>(text, b1, b2);
    conv_kernel<<<MROWS, 256>>>(cw1, cb1, cw2, cb2, out);
}

// round 10
// speedup vs baseline: 1.0066x; 1.0038x over previous
#include <cuda_runtime.h>
#include <cuda_fp16.h>
#include <cstdint>

// ---------------- problem constants ----------------
#define BB 4096
#define VV 20
#define DD 768
#define MROWS (BB * VV)        // 81920
#define NN (2 * DD)            // 1536 interleaved (m1,m2)
#define KK DD                  // 768

// ---------------- scratch (static device globals; no allocations) ----------------
__device__ __half g_Xn[(size_t)MROWS * DD];    // softmaxed A, fp16 (126 MB)
__device__ __half g_Wc[(size_t)NN * DD];       // interleaved weights fp16 (2.4 MB)
__device__ __half g_Fused[(size_t)MROWS * DD]; // relu(text*m1+m2), fp16 (126 MB)

// ---------------- baseline-PTX helpers ----------------
__device__ __forceinline__ uint32_t smem_u32(const void* p) {
    uint32_t a;
    asm("{ .reg .u64 t; cvta.to.shared.u64 t, %1; cvt.u32.u64 %0, t; }" : "=r"(a) : "l"(p));
    return a;
}
__device__ __forceinline__ void cp_async16(uint32_t saddr, const void* gptr) {
    asm volatile("cp.async.cg.shared.global [%0], [%1], 16;\n" :: "r"(saddr), "l"(gptr));
}
#define CP_COMMIT() asm volatile("cp.async.commit_group;\n" ::: "memory")
#define CP_WAIT_1() asm volatile("cp.async.wait_group 1;\n" ::: "memory")
#define CP_WAIT_0() asm volatile("cp.async.wait_group 0;\n" ::: "memory")

__device__ __forceinline__ void ldsm_x4(uint32_t& r0, uint32_t& r1, uint32_t& r2, uint32_t& r3,
                                        uint32_t addr) {
    asm volatile("ldmatrix.sync.aligned.m8n8.x4.shared.b16 {%0,%1,%2,%3}, [%4];"
                 : "=r"(r0), "=r"(r1), "=r"(r2), "=r"(r3) : "r"(addr));
}
__device__ __forceinline__ void mma16816(float* c, const uint32_t* a, uint32_t b0, uint32_t b1) {
    asm volatile(
        "mma.sync.aligned.m16n8k16.row.col.f32.f16.f16.f32 "
        "{%0,%1,%2,%3}, {%4,%5,%6,%7}, {%8,%9}, {%0,%1,%2,%3};"
        : "+f"(c[0]), "+f"(c[1]), "+f"(c[2]), "+f"(c[3])
        : "r"(a[0]), "r"(a[1]), "r"(a[2]), "r"(a[3]), "r"(b0), "r"(b1));
}

// ---------------- kernel 1: interleave + cast weights ----------------
__global__ void prep_w(const float* __restrict__ W1, const float* __restrict__ W2) {
    int idx = blockIdx.x * blockDim.x + threadIdx.x;
    if (idx >= NN * DD) return;
    int n = idx / DD, k = idx - n * DD;
    int e = n >> 1;
    float v = (n & 1) ? W2[e * DD + k] : W1[e * DD + k];
    g_Wc[idx] = __float2half_rn(v);
}

// ---------------- kernel 2: row softmax -> fp16 ----------------
__global__ void __launch_bounds__(256) softmax_rows(const float* __restrict__ vf) {
    int row = blockIdx.x;
    int tid = threadIdx.x;
    const float* x = vf + (size_t)row * DD;
    float a = x[tid], b = x[tid + 256], c = x[tid + 512];
    float m = fmaxf(a, fmaxf(b, c));
    #pragma unroll
    for (int o = 16; o; o >>= 1) m = fmaxf(m, __shfl_xor_sync(0xffffffffu, m, o));
    __shared__ float red[8];
    __shared__ float bc_max, bc_inv;
    int w = tid >> 5;
    if ((tid & 31) == 0) red[w] = m;
    __syncthreads();
    if (tid == 0) {
        float t = red[0];
        #pragma unroll
        for (int i = 1; i < 8; i++) t = fmaxf(t, red[i]);
        bc_max = t;
    }
    __syncthreads();
    float M_ = bc_max;
    float e0 = __expf(a - M_), e1 = __expf(b - M_), e2 = __expf(c - M_);
    float s = e0 + e1 + e2;
    #pragma unroll
    for (int o = 16; o; o >>= 1) s += __shfl_xor_sync(0xffffffffu, s, o);
    __syncthreads();
    if ((tid & 31) == 0) red[w] = s;
    __syncthreads();
    if (tid == 0) {
        float t = 0.f;
        #pragma unroll
        for (int i = 0; i < 8; i++) t += red[i];
        bc_inv = 1.f / t;
    }
    __syncthreads();
    float inv = bc_inv;
    __half* dst = g_Xn + (size_t)row * DD;
    dst[tid]       = __float2half_rn(e0 * inv);
    dst[tid + 256] = __float2half_rn(e1 * inv);
    dst[tid + 512] = __float2half_rn(e2 * inv);
}

// ---------------- kernel 3: fp16 HMMA GEMM + fused bias/relu epilogue ----------------
// EXACT round-2 loop structure (best measured): load next -> wait -> sync -> MMA -> sync
#define TM 128
#define TN 128
#define KC 64                              // 64 fp16 = 128B row
#define NKC (KK / KC)                      // 12
#define A_BYTES (TM * 128)                 // 16384
#define B_BYTES (TN * 128)                 // 16384
#define STAGE_BYTES (A_BYTES + B_BYTES)    // 32768
#define SM_TOTAL (2 * STAGE_BYTES)         // 65536

__device__ __forceinline__ uint32_t sw128(uint32_t off) {
    return off ^ ((off >> 3) & 0x70);
}

__device__ __forceinline__ void load_stage(uint32_t sbase, int s, int kc, int tid,
                                           const __half* Ab, const __half* Bw) {
    uint32_t abase = sbase + s * STAGE_BYTES;
    uint32_t bbase = abase + A_BYTES;
    #pragma unroll
    for (int t = 0; t < 4; t++) {
        int idx = tid + t * 256;
        int r = idx >> 3, i = idx & 7;
        uint32_t off = (uint32_t)(r * 128 + i * 16);
        cp_async16(abase + sw128(off), (const char*)(Ab + (size_t)r * DD + kc * KC) + i * 16);
    }
    #pragma unroll
    for (int t = 0; t < 4; t++) {
        int idx = tid + t * 256;
        int r = idx >> 3, i = idx & 7;
        uint32_t off = (uint32_t)(r * 128 + i * 16);
        cp_async16(bbase + sw128(off), (const char*)(Bw + (size_t)r * DD + kc * KC) + i * 16);
    }
    CP_COMMIT();
}

__global__ void __launch_bounds__(256) gemm_kernel(const float* __restrict__ text,
                                                   const float* __restrict__ b1,
                                                   const float* __restrict__ b2) {
    extern __shared__ char smem[];
    uint32_t sbase = smem_u32(smem);
    int tid = threadIdx.x, wid = tid >> 5, lane = tid & 31;
    int mw = wid & 3, nw = wid >> 2;           // warp grid 4(m) x 2(n), warp tile 32x64
    int n0 = blockIdx.x * TN;
    int m0 = blockIdx.y * TM;

    const __half* Ab = g_Xn + (size_t)m0 * DD;
    const __half* Bw = g_Wc + (size_t)n0 * DD;

    float acc[2][8][4];
    #pragma unroll
    for (int i = 0; i < 2; i++)
        #pragma unroll
        for (int j = 0; j < 8; j++)
            #pragma unroll
            for (int q = 0; q < 4; q++) acc[i][j][q] = 0.f;

    load_stage(sbase, 0, 0, tid, Ab, Bw);

    const uint32_t a_row_off = (uint32_t)((mw * 32 + (lane & 15)) * 128 + ((lane >> 4) * 16));
    const uint32_t b_row_base = (uint32_t)((nw * 64 + (lane & 7) + (((lane >> 4) & 1) << 3)) * 128
                                           + (((lane >> 3) & 1) * 16));

    for (int c = 0; c < NKC; c++) {
        int s = c & 1;
        if (c + 1 < NKC) {
            load_stage(sbase, s ^ 1, c + 1, tid, Ab, Bw);
            CP_WAIT_1();
        } else {
            CP_WAIT_0();
        }
        __syncthreads();

        uint32_t abase = sbase + s * STAGE_BYTES;
        uint32_t bbase = abase + A_BYTES;
        #pragma unroll
        for (int ks = 0; ks < 4; ks++) {
            uint32_t a[2][4];
            #pragma unroll
            for (int mf = 0; mf < 2; mf++)
                ldsm_x4(a[mf][0], a[mf][1], a[mf][2], a[mf][3],
                        abase + sw128(a_row_off + mf * 16 * 128 + ks * 32));
            #pragma unroll
            for (int nf2 = 0; nf2 < 4; nf2++) {
                uint32_t r0, r1, r2, r3;
                ldsm_x4(r0, r1, r2, r3,
                        bbase + sw128(b_row_base + nf2 * 16 * 128 + ks * 32));
                mma16816(acc[0][nf2 * 2],     a[0], r0, r1);
                mma16816(acc[0][nf2 * 2 + 1], a[0], r2, r3);
                mma16816(acc[1][nf2 * 2],     a[1], r0, r1);
                mma16816(acc[1][nf2 * 2 + 1], a[1], r2, r3);
            }
        }
        __syncthreads();
    }

    // fused epilogue: relu(text*(m1+b1) + (m2+b2)) -> g_Fused (fp16)
    #pragma unroll
    for (int mf = 0; mf < 2; mf++) {
        int m_a = m0 + mw * 32 + mf * 16 + (lane >> 2);
        int m_b = m_a + 8;
        const float* trow_a = text + (size_t)(m_a / VV) * DD;
        const float* trow_b = text + (size_t)(m_b / VV) * DD;
        #pragma unroll
        for (int nf = 0; nf < 8; nf++) {
            int e = ((n0 + nw * 64 + nf * 8) >> 1) + (lane & 3);
            float bb1 = __ldg(b1 + e), bb2 = __ldg(b2 + e);
            float va = fmaxf(fmaf(__ldg(trow_a + e), acc[mf][nf][0] + bb1,
                                  acc[mf][nf][1] + bb2), 0.f);
            float vb = fmaxf(fmaf(__ldg(trow_b + e), acc[mf][nf][2] + bb1,
                                  acc[mf][nf][3] + bb2), 0.f);
            g_Fused[(size_t)m_a * DD + e] = __float2half_rn(va);
            g_Fused[(size_t)m_b * DD + e] = __float2half_rn(vb);
        }
    }
}

// ---------------- kernel 4: conv3 -> relu -> conv3, 8 rows/block, vectorized ----------------
#define CROWS 8
__global__ void __launch_bounds__(256) conv_kernel(const float* __restrict__ cw1,
                                                   const float* __restrict__ cb1,
                                                   const float* __restrict__ cw2,
                                                   const float* __restrict__ cb2,
                                                   float* __restrict__ out) {
    __shared__ float s1[CROWS][DD];
    __shared__ float s2[CROWS][DD];
    int tid = threadIdx.x;
    size_t row0 = (size_t)blockIdx.x * CROWS;
    float w10 = __ldg(cw1), w11 = __ldg(cw1 + 1), w12 = __ldg(cw1 + 2), bb1 = __ldg(cb1);
    float w20 = __ldg(cw2), w21 = __ldg(cw2 + 1), w22 = __ldg(cw2 + 2), bb2 = __ldg(cb2);

    // load 8 rows of fp16 as uint4 (8 halfs): 8*768/8 = 768 chunks, 3/thread
    const uint4* src = (const uint4*)(g_Fused + row0 * DD);
    #pragma unroll
    for (int t = 0; t < 3; t++) {
        int i = tid + t * 256;
        uint4 v = src[i];
        int r = i / 96, c8 = (i % 96) * 8;
        const __half2* h = (const __half2*)&v;
        #pragma unroll
        for (int j = 0; j < 4; j++) {
            float2 f = __half22float2(h[j]);
            s1[r][c8 + 2 * j]     = f.x;
            s1[r][c8 + 2 * j + 1] = f.y;
        }
    }
    __syncthreads();

    // conv1 + relu: 8*768 = 6144 elements, 24/thread
    #pragma unroll 4
    for (int i = tid; i < CROWS * DD; i += 256) {
        int r = i / DD, c = i - r * DD;
        float l = (c > 0)      ? s1[r][c - 1] : 0.f;
        float rr = (c < DD - 1) ? s1[r][c + 1] : 0.f;
        s2[r][c] = fmaxf(w10 * l + w11 * s1[r][c] + w12 * rr + bb1, 0.f);
    }
    __syncthreads();

    // conv2 -> out via float4: 8*192 = 1536 chunks, 6/thread
    float4* dst = (float4*)(out + row0 * DD);
    #pragma unroll
    for (int t = 0; t < 6; t++) {
        int i4 = tid + t * 256;
        int r = i4 / (DD / 4), c = (i4 - r * (DD / 4)) * 4;
        float4 o;
        {
            float l = (c > 0) ? s2[r][c - 1] : 0.f;
            o.x = w20 * l + w21 * s2[r][c] + w22 * s2[r][c + 1] + bb2;
        }
        o.y = w20 * s2[r][c] + w21 * s2[r][c + 1] + w22 * s2[r][c + 2] + bb2;
        o.z = w20 * s2[r][c + 1] + w21 * s2[r][c + 2] + w22 * s2[r][c + 3] + bb2;
        {
            float rr = (c + 4 < DD) ? s2[r][c + 4] : 0.f;
            o.w = w20 * s2[r][c + 2] + w21 * s2[r][c + 3] + w22 * rr + bb2;
        }
        dst[i4] = o;
    }
}

// ---------------- launch (single stream) ----------------
extern "C" void kernel_launch(void* const* d_in, const int* in_sizes, int n_in,
                              void* d_out, int out_size) {
    const float* text = (const float*)d_in[0];
    const float* vf   = (const float*)d_in[1];
    const float* W1   = (const float*)d_in[2];
    const float* b1   = (const float*)d_in[3];
    const float* W2   = (const float*)d_in[4];
    const float* b2   = (const float*)d_in[5];
    const float* cw1  = (const float*)d_in[6];
    const float* cb1  = (const float*)d_in[7];
    const float* cw2  = (const float*)d_in[8];
    const float* cb2  = (const float*)d_in[9];
    float* out = (float*)d_out;

    cudaFuncSetAttribute(gemm_kernel, cudaFuncAttributeMaxDynamicSharedMemorySize, SM_TOTAL);

    prep_w<<<(NN * DD + 255) / 256, 256>>>(W1, W2);
    softmax_rows<<<MROWS, 256>>>(vf);
    gemm_kernel<<<dim3(NN / TN, MROWS / TM), 256, SM_TOTAL>>>(text, b1, b2);
    conv_kernel<<<MROWS / CROWS, 256>>>(cw1, cb1, cw2, cb2, out);
}

// round 11
// speedup vs baseline: 1.0297x; 1.0230x over previous
#include <cuda_runtime.h>
#include <cuda_bf16.h>
#include <cuda_fp16.h>
#include <cstdint>

// ---------------- problem constants ----------------
#define BB 4096
#define VV 20
#define DD 768
#define MROWS (BB * VV)        // 81920
#define NN (2 * DD)            // 1536 interleaved (m1,m2)
#define KK DD                  // 768

// ---------------- scratch (static device globals; no allocations) ----------------
__device__ __nv_bfloat16 g_Xn[(size_t)MROWS * DD];   // softmaxed A, bf16 (126 MB)
__device__ __nv_bfloat16 g_Wc[(size_t)NN * DD];      // interleaved weights bf16 (2.4 MB)
__device__ __half        g_Fused[(size_t)MROWS * DD];// relu(text*m1+m2), fp16 (126 MB)

// ---------------- baseline-PTX helpers ----------------
__device__ __forceinline__ uint32_t smem_u32(const void* p) {
    uint32_t a;
    asm("{ .reg .u64 t; cvta.to.shared.u64 t, %1; cvt.u32.u64 %0, t; }" : "=r"(a) : "l"(p));
    return a;
}
__device__ __forceinline__ void cp_async16(uint32_t saddr, const void* gptr) {
    asm volatile("cp.async.cg.shared.global [%0], [%1], 16;\n" :: "r"(saddr), "l"(gptr));
}
#define CP_COMMIT() asm volatile("cp.async.commit_group;\n" ::: "memory")
#define CP_WAIT_1() asm volatile("cp.async.wait_group 1;\n" ::: "memory")
#define CP_WAIT_0() asm volatile("cp.async.wait_group 0;\n" ::: "memory")

__device__ __forceinline__ void ldsm_x4(uint32_t& r0, uint32_t& r1, uint32_t& r2, uint32_t& r3,
                                        uint32_t addr) {
    asm volatile("ldmatrix.sync.aligned.m8n8.x4.shared.b16 {%0,%1,%2,%3}, [%4];"
                 : "=r"(r0), "=r"(r1), "=r"(r2), "=r"(r3) : "r"(addr));
}
__device__ __forceinline__ void mma16816(float* c, const uint32_t* a, const uint32_t* b) {
    asm volatile(
        "mma.sync.aligned.m16n8k16.row.col.f32.bf16.bf16.f32 "
        "{%0,%1,%2,%3}, {%4,%5,%6,%7}, {%8,%9}, {%0,%1,%2,%3};"
        : "+f"(c[0]), "+f"(c[1]), "+f"(c[2]), "+f"(c[3])
        : "r"(a[0]), "r"(a[1]), "r"(a[2]), "r"(a[3]), "r"(b[0]), "r"(b[1]));
}

// ---------------- kernel 1: interleave + cast weights ----------------
__global__ void prep_w(const float* __restrict__ W1, const float* __restrict__ W2) {
    int idx = blockIdx.x * blockDim.x + threadIdx.x;
    if (idx >= NN * DD) return;
    int n = idx / DD, k = idx - n * DD;
    int e = n >> 1;
    float v = (n & 1) ? W2[e * DD + k] : W1[e * DD + k];
    g_Wc[idx] = __float2bfloat16(v);
}

// ---------------- kernel 2: row softmax -> bf16 ----------------
__global__ void __launch_bounds__(256) softmax_rows(const float* __restrict__ vf) {
    int row = blockIdx.x;
    int tid = threadIdx.x;
    const float* x = vf + (size_t)row * DD;
    float a = x[tid], b = x[tid + 256], c = x[tid + 512];
    float m = fmaxf(a, fmaxf(b, c));
    #pragma unroll
    for (int o = 16; o; o >>= 1) m = fmaxf(m, __shfl_xor_sync(0xffffffffu, m, o));
    __shared__ float red[8];
    __shared__ float bc_max, bc_inv;
    int w = tid >> 5;
    if ((tid & 31) == 0) red[w] = m;
    __syncthreads();
    if (tid == 0) {
        float t = red[0];
        #pragma unroll
        for (int i = 1; i < 8; i++) t = fmaxf(t, red[i]);
        bc_max = t;
    }
    __syncthreads();
    float M_ = bc_max;
    float e0 = __expf(a - M_), e1 = __expf(b - M_), e2 = __expf(c - M_);
    float s = e0 + e1 + e2;
    #pragma unroll
    for (int o = 16; o; o >>= 1) s += __shfl_xor_sync(0xffffffffu, s, o);
    __syncthreads();
    if ((tid & 31) == 0) red[w] = s;
    __syncthreads();
    if (tid == 0) {
        float t = 0.f;
        #pragma unroll
        for (int i = 0; i < 8; i++) t += red[i];
        bc_inv = 1.f / t;
    }
    __syncthreads();
    float inv = bc_inv;
    __nv_bfloat16* dst = g_Xn + (size_t)row * DD;
    dst[tid]       = __float2bfloat16(e0 * inv);
    dst[tid + 256] = __float2bfloat16(e1 * inv);
    dst[tid + 512] = __float2bfloat16(e2 * inv);
}

// ---------------- kernel 3: bf16 HMMA GEMM (exact R2 inner loop) + fused epilogue ----------
#define TM 128
#define TN 128
#define KC 64                              // 64 bf16 = 128B row
#define NKC (KK / KC)                      // 12
#define A_BYTES (TM * 128)                 // 16384
#define B_BYTES (TN * 128)                 // 16384
#define STAGE_BYTES (A_BYTES + B_BYTES)    // 32768
#define SM_TOTAL (2 * STAGE_BYTES)         // 65536

__device__ __forceinline__ uint32_t sw128(uint32_t off) {
    return off ^ ((off >> 3) & 0x70);
}

__device__ __forceinline__ void load_stage(uint32_t sbase, int s, int kc, int tid,
                                           const __nv_bfloat16* Ab, const __nv_bfloat16* Bw) {
    uint32_t abase = sbase + s * STAGE_BYTES;
    uint32_t bbase = abase + A_BYTES;
    #pragma unroll
    for (int t = 0; t < 4; t++) {
        int idx = tid + t * 256;
        int r = idx >> 3, i = idx & 7;
        uint32_t off = (uint32_t)(r * 128 + i * 16);
        cp_async16(abase + sw128(off), (const char*)(Ab + (size_t)r * DD + kc * KC) + i * 16);
    }
    #pragma unroll
    for (int t = 0; t < 4; t++) {
        int idx = tid + t * 256;
        int r = idx >> 3, i = idx & 7;
        uint32_t off = (uint32_t)(r * 128 + i * 16);
        cp_async16(bbase + sw128(off), (const char*)(Bw + (size_t)r * DD + kc * KC) + i * 16);
    }
    CP_COMMIT();
}

__global__ void __launch_bounds__(256) gemm_kernel(const float* __restrict__ text,
                                                   const float* __restrict__ b1,
                                                   const float* __restrict__ b2) {
    extern __shared__ char smem[];
    uint32_t sbase = smem_u32(smem);
    int tid = threadIdx.x, wid = tid >> 5, lane = tid & 31;
    int mw = wid & 3, nw = wid >> 2;           // warp grid 4(m) x 2(n), warp tile 32x64
    int n0 = blockIdx.x * TN;
    int m0 = blockIdx.y * TM;

    const __nv_bfloat16* Ab = g_Xn + (size_t)m0 * DD;
    const __nv_bfloat16* Bw = g_Wc + (size_t)n0 * DD;

    float acc[2][8][4];
    #pragma unroll
    for (int i = 0; i < 2; i++)
        #pragma unroll
        for (int j = 0; j < 8; j++)
            #pragma unroll
            for (int q = 0; q < 4; q++) acc[i][j][q] = 0.f;

    load_stage(sbase, 0, 0, tid, Ab, Bw);

    for (int c = 0; c < NKC; c++) {
        int s = c & 1;
        if (c + 1 < NKC) {
            load_stage(sbase, s ^ 1, c + 1, tid, Ab, Bw);
            CP_WAIT_1();
        } else {
            CP_WAIT_0();
        }
        __syncthreads();

        uint32_t abase = sbase + s * STAGE_BYTES;
        uint32_t bbase = abase + A_BYTES;
        #pragma unroll
        for (int ks = 0; ks < 4; ks++) {
            uint32_t a[2][4];
            #pragma unroll
            for (int mf = 0; mf < 2; mf++) {
                int row = mw * 32 + mf * 16 + (lane & 15);
                uint32_t off = (uint32_t)(row * 128 + ((lane >> 4) * 16) + ks * 32);
                ldsm_x4(a[mf][0], a[mf][1], a[mf][2], a[mf][3], abase + sw128(off));
            }
            uint32_t b[8][2];
            #pragma unroll
            for (int nf2 = 0; nf2 < 4; nf2++) {
                int nrow = nw * 64 + nf2 * 16 + (lane & 7) + (((lane >> 4) & 1) << 3);
                uint32_t off = (uint32_t)(nrow * 128 + (((lane >> 3) & 1) * 16) + ks * 32);
                uint32_t r0, r1, r2, r3;
                ldsm_x4(r0, r1, r2, r3, bbase + sw128(off));
                b[nf2 * 2][0] = r0;     b[nf2 * 2][1] = r1;
                b[nf2 * 2 + 1][0] = r2; b[nf2 * 2 + 1][1] = r3;
            }
            #pragma unroll
            for (int mf = 0; mf < 2; mf++)
                #pragma unroll
                for (int nf = 0; nf < 8; nf++)
                    mma16816(acc[mf][nf], a[mf], b[nf]);
        }
        __syncthreads();
    }

    // fused epilogue: relu(text*(m1+b1) + (m2+b2)) -> g_Fused (fp16)
    #pragma unroll
    for (int mf = 0; mf < 2; mf++) {
        int m_a = m0 + mw * 32 + mf * 16 + (lane >> 2);
        int m_b = m_a + 8;
        const float* trow_a = text + (size_t)(m_a / VV) * DD;
        const float* trow_b = text + (size_t)(m_b / VV) * DD;
        #pragma unroll
        for (int nf = 0; nf < 8; nf++) {
            int e = ((n0 + nw * 64 + nf * 8) >> 1) + (lane & 3);
            float bb1 = __ldg(b1 + e), bb2 = __ldg(b2 + e);
            float va = fmaxf(fmaf(__ldg(trow_a + e), acc[mf][nf][0] + bb1,
                                  acc[mf][nf][1] + bb2), 0.f);
            float vb = fmaxf(fmaf(__ldg(trow_b + e), acc[mf][nf][2] + bb1,
                                  acc[mf][nf][3] + bb2), 0.f);
            g_Fused[(size_t)m_a * DD + e] = __float2half_rn(va);
            g_Fused[(size_t)m_b * DD + e] = __float2half_rn(vb);
        }
    }
}

// ---------------- kernel 4: conv3 -> relu -> conv3, 4 rows/block, vectorized ----------------
#define CROWS 4
__global__ void __launch_bounds__(256) conv_kernel(const float* __restrict__ cw1,
                                                   const float* __restrict__ cb1,
                                                   const float* __restrict__ cw2,
                                                   const float* __restrict__ cb2,
                                                   float* __restrict__ out) {
    __shared__ float s1[CROWS][DD];
    __shared__ float s2[CROWS][DD];
    int tid = threadIdx.x;
    size_t row0 = (size_t)blockIdx.x * CROWS;
    float w10 = __ldg(cw1), w11 = __ldg(cw1 + 1), w12 = __ldg(cw1 + 2), bb1 = __ldg(cb1);
    float w20 = __ldg(cw2), w21 = __ldg(cw2 + 1), w22 = __ldg(cw2 + 2), bb2 = __ldg(cb2);

    // load 4 rows of fp16 as uint4 (8 halfs): 4*768/8 = 384 chunks
    const uint4* src = (const uint4*)(g_Fused + row0 * DD);
    #pragma unroll
    for (int t = 0; t < 2; t++) {
        int i = tid + t * 256;
        if (i < CROWS * DD / 8) {
            uint4 v = src[i];
            int r = i / 96, c8 = (i % 96) * 8;
            const __half2* h = (const __half2*)&v;
            #pragma unroll
            for (int j = 0; j < 4; j++) {
                float2 f = __half22float2(h[j]);
                s1[r][c8 + 2 * j]     = f.x;
                s1[r][c8 + 2 * j + 1] = f.y;
            }
        }
    }
    __syncthreads();

    // conv1 + relu: 4*768 = 3072 elements, 12/thread
    #pragma unroll 4
    for (int i = tid; i < CROWS * DD; i += 256) {
        int r = i / DD, c = i - r * DD;
        float l = (c > 0)      ? s1[r][c - 1] : 0.f;
        float rr = (c < DD - 1) ? s1[r][c + 1] : 0.f;
        s2[r][c] = fmaxf(w10 * l + w11 * s1[r][c] + w12 * rr + bb1, 0.f);
    }
    __syncthreads();

    // conv2 -> out via float4: 4*192 = 768 chunks, 3/thread
    float4* dst = (float4*)(out + row0 * DD);
    #pragma unroll
    for (int t = 0; t < 3; t++) {
        int i4 = tid + t * 256;
        int r = i4 / (DD / 4), c = (i4 - r * (DD / 4)) * 4;
        float4 o;
        {
            float l = (c > 0) ? s2[r][c - 1] : 0.f;
            o.x = w20 * l + w21 * s2[r][c] + w22 * s2[r][c + 1] + bb2;
        }
        o.y = w20 * s2[r][c] + w21 * s2[r][c + 1] + w22 * s2[r][c + 2] + bb2;
        o.z = w20 * s2[r][c + 1] + w21 * s2[r][c + 2] + w22 * s2[r][c + 3] + bb2;
        {
            float rr = (c + 4 < DD) ? s2[r][c + 4] : 0.f;
            o.w = w20 * s2[r][c + 2] + w21 * s2[r][c + 3] + w22 * rr + bb2;
        }
        dst[i4] = o;
    }
}

// ---------------- launch (single stream) ----------------
extern "C" void kernel_launch(void* const* d_in, const int* in_sizes, int n_in,
                              void* d_out, int out_size) {
    const float* text = (const float*)d_in[0];
    const float* vf   = (const float*)d_in[1];
    const float* W1   = (const float*)d_in[2];
    const float* b1   = (const float*)d_in[3];
    const float* W2   = (const float*)d_in[4];
    const float* b2   = (const float*)d_in[5];
    const float* cw1  = (const float*)d_in[6];
    const float* cb1  = (const float*)d_in[7];
    const float* cw2  = (const float*)d_in[8];
    const float* cb2  = (const float*)d_in[9];
    float* out = (float*)d_out;

    cudaFuncSetAttribute(gemm_kernel, cudaFuncAttributeMaxDynamicSharedMemorySize, SM_TOTAL);

    prep_w<<<(NN * DD + 255) / 256, 256>>>(W1, W2);
    softmax_rows<<<MROWS, 256>>>(vf);
    gemm_kernel<<<dim3(NN / TN, MROWS / TM), 256, SM_TOTAL>>>(text, b1, b2);
    conv_kernel<<<MROWS / CROWS, 256>>>(cw1, cb1, cw2, cb2, out);
}

// round 12
// speedup vs baseline: 1.1378x; 1.1050x over previous
#include <cuda_runtime.h>
#include <cuda_bf16.h>
#include <cstdint>

// ---------------- problem constants ----------------
#define BB 4096
#define VV 20
#define DD 768
#define MROWS (BB * VV)        // 81920
#define NN (2 * DD)            // 1536 interleaved (m1,m2)
#define KK DD                  // 768
#define NEB (DD / 64)          // 12 e-blocks of 64

// ---------------- scratch (static device globals; no allocations) ----------------
__device__ __nv_bfloat16 g_Xn[(size_t)MROWS * DD];   // softmaxed A, bf16 (126 MB)
__device__ __nv_bfloat16 g_Wc[(size_t)NN * DD];      // interleaved weights bf16 (2.4 MB)
__device__ float g_Halo[(size_t)MROWS * (NEB * 8)];  // fused halo cols, 8/block (31.5 MB)

// ---------------- baseline-PTX helpers ----------------
__device__ __forceinline__ uint32_t smem_u32(const void* p) {
    uint32_t a;
    asm("{ .reg .u64 t; cvta.to.shared.u64 t, %1; cvt.u32.u64 %0, t; }" : "=r"(a) : "l"(p));
    return a;
}
__device__ __forceinline__ void cp_async16(uint32_t saddr, const void* gptr) {
    asm volatile("cp.async.cg.shared.global [%0], [%1], 16;\n" :: "r"(saddr), "l"(gptr));
}
#define CP_COMMIT() asm volatile("cp.async.commit_group;\n" ::: "memory")
#define CP_WAIT_1() asm volatile("cp.async.wait_group 1;\n" ::: "memory")
#define CP_WAIT_0() asm volatile("cp.async.wait_group 0;\n" ::: "memory")

__device__ __forceinline__ void ldsm_x4(uint32_t& r0, uint32_t& r1, uint32_t& r2, uint32_t& r3,
                                        uint32_t addr) {
    asm volatile("ldmatrix.sync.aligned.m8n8.x4.shared.b16 {%0,%1,%2,%3}, [%4];"
                 : "=r"(r0), "=r"(r1), "=r"(r2), "=r"(r3) : "r"(addr));
}
__device__ __forceinline__ void mma16816(float* c, const uint32_t* a, const uint32_t* b) {
    asm volatile(
        "mma.sync.aligned.m16n8k16.row.col.f32.bf16.bf16.f32 "
        "{%0,%1,%2,%3}, {%4,%5,%6,%7}, {%8,%9}, {%0,%1,%2,%3};"
        : "+f"(c[0]), "+f"(c[1]), "+f"(c[2]), "+f"(c[3])
        : "r"(a[0]), "r"(a[1]), "r"(a[2]), "r"(a[3]), "r"(b[0]), "r"(b[1]));
}

// ---------------- kernel 1: interleave + cast weights ----------------
__global__ void prep_w(const float* __restrict__ W1, const float* __restrict__ W2) {
    int idx = blockIdx.x * blockDim.x + threadIdx.x;
    if (idx >= NN * DD) return;
    int n = idx / DD, k = idx - n * DD;
    int e = n >> 1;
    float v = (n & 1) ? W2[e * DD + k] : W1[e * DD + k];
    g_Wc[idx] = __float2bfloat16(v);
}

// ---------------- kernel 2: warp-per-row softmax -> bf16 ----------------
__global__ void __launch_bounds__(256) softmax_rows(const float* __restrict__ vf) {
    int wid = threadIdx.x >> 5, lane = threadIdx.x & 31;
    int row = blockIdx.x * 8 + wid;
    const float4* x4 = (const float4*)(vf + (size_t)row * DD);   // 192 float4/row
    float v[24];
    #pragma unroll
    for (int j = 0; j < 6; j++) {
        float4 f = x4[lane + 32 * j];
        v[4 * j] = f.x; v[4 * j + 1] = f.y; v[4 * j + 2] = f.z; v[4 * j + 3] = f.w;
    }
    float m = v[0];
    #pragma unroll
    for (int i = 1; i < 24; i++) m = fmaxf(m, v[i]);
    #pragma unroll
    for (int o = 16; o; o >>= 1) m = fmaxf(m, __shfl_xor_sync(0xffffffffu, m, o));
    float s = 0.f;
    #pragma unroll
    for (int i = 0; i < 24; i++) { v[i] = __expf(v[i] - m); s += v[i]; }
    #pragma unroll
    for (int o = 16; o; o >>= 1) s += __shfl_xor_sync(0xffffffffu, s, o);
    float inv = 1.f / s;

    __shared__ __nv_bfloat162 st[8][DD / 2];       // 8 rows staging, 12 KB
    #pragma unroll
    for (int j = 0; j < 6; j++) {
        int f = lane + 32 * j;                     // float4 index
        st[wid][2 * f]     = __floats2bfloat162_rn(v[4 * j] * inv,     v[4 * j + 1] * inv);
        st[wid][2 * f + 1] = __floats2bfloat162_rn(v[4 * j + 2] * inv, v[4 * j + 3] * inv);
    }
    __syncwarp();
    uint4* dst = (uint4*)(g_Xn + (size_t)row * DD);   // 96 uint4/row
    const uint4* srow = (const uint4*)st[wid];
    #pragma unroll
    for (int j = 0; j < 3; j++) {
        int i = lane + 32 * j;
        dst[i] = srow[i];
    }
}

// ---------------- kernel 3: bf16 GEMM (TN=128, no halo) + fused bias/relu/conv epilogue ----
#define TM 128
#define TN 128
#define KC 64
#define NKC (KK / KC)                      // 12
#define A_BYTES (TM * 128)
#define B_BYTES (TN * 128)
#define STAGE_BYTES (A_BYTES + B_BYTES)    // 32768
#define SM_TOTAL (2 * STAGE_BYTES)         // 65536
// epilogue planes (alias stages): SF [128][64] fp32 (32768 B), SC [128][63] fp32 (32256 B)
#define SF_STRIDE 64
#define SC_STRIDE 63

__device__ __forceinline__ uint32_t sw128(uint32_t off) {
    return off ^ ((off >> 3) & 0x70);
}

__device__ __forceinline__ void load_stage(uint32_t sbase, int s, int kc, int tid,
                                           const __nv_bfloat16* Ab, const __nv_bfloat16* Bw) {
    uint32_t abase = sbase + s * STAGE_BYTES;
    uint32_t bbase = abase + A_BYTES;
    #pragma unroll
    for (int t = 0; t < 4; t++) {
        int idx = tid + t * 256;
        int r = idx >> 3, i = idx & 7;
        uint32_t off = (uint32_t)(r * 128 + i * 16);
        cp_async16(abase + sw128(off), (const char*)(Ab + (size_t)r * DD + kc * KC) + i * 16);
    }
    #pragma unroll
    for (int t = 0; t < 4; t++) {
        int idx = tid + t * 256;
        int r = idx >> 3, i = idx & 7;
        uint32_t off = (uint32_t)(r * 128 + i * 16);
        cp_async16(bbase + sw128(off), (const char*)(Bw + (size_t)r * DD + kc * KC) + i * 16);
    }
    CP_COMMIT();
}

__global__ void __launch_bounds__(256) gemm_fused_kernel(const float* __restrict__ text,
                                                         const float* __restrict__ b1,
                                                         const float* __restrict__ b2,
                                                         const float* __restrict__ cw1,
                                                         const float* __restrict__ cb1,
                                                         const float* __restrict__ cw2,
                                                         const float* __restrict__ cb2,
                                                         float* __restrict__ out) {
    extern __shared__ char smem[];
    uint32_t sbase = smem_u32(smem);
    int tid = threadIdx.x, wid = tid >> 5, lane = tid & 31;
    int mw = wid & 3, nw = wid >> 2;           // warp grid 4(m) x 2(n), warp tile 32x64
    int eb = blockIdx.x;                       // e-block
    int n0 = eb * TN;
    int m0 = blockIdx.y * TM;

    const __nv_bfloat16* Ab = g_Xn + (size_t)m0 * DD;
    const __nv_bfloat16* Bw = g_Wc + (size_t)n0 * DD;

    float acc[2][8][4];
    #pragma unroll
    for (int i = 0; i < 2; i++)
        #pragma unroll
        for (int j = 0; j < 8; j++)
            #pragma unroll
            for (int q = 0; q < 4; q++) acc[i][j][q] = 0.f;

    load_stage(sbase, 0, 0, tid, Ab, Bw);

    for (int c = 0; c < NKC; c++) {
        int s = c & 1;
        if (c + 1 < NKC) {
            load_stage(sbase, s ^ 1, c + 1, tid, Ab, Bw);
            CP_WAIT_1();
        } else {
            CP_WAIT_0();
        }
        __syncthreads();

        uint32_t abase = sbase + s * STAGE_BYTES;
        uint32_t bbase = abase + A_BYTES;
        #pragma unroll
        for (int ks = 0; ks < 4; ks++) {
            uint32_t a[2][4];
            #pragma unroll
            for (int mf = 0; mf < 2; mf++) {
                int row = mw * 32 + mf * 16 + (lane & 15);
                uint32_t off = (uint32_t)(row * 128 + ((lane >> 4) * 16) + ks * 32);
                ldsm_x4(a[mf][0], a[mf][1], a[mf][2], a[mf][3], abase + sw128(off));
            }
            uint32_t b[8][2];
            #pragma unroll
            for (int nf2 = 0; nf2 < 4; nf2++) {
                int nrow = nw * 64 + nf2 * 16 + (lane & 7) + (((lane >> 4) & 1) << 3);
                uint32_t off = (uint32_t)(nrow * 128 + (((lane >> 3) & 1) * 16) + ks * 32);
                uint32_t r0, r1, r2, r3;
                ldsm_x4(r0, r1, r2, r3, bbase + sw128(off));
                b[nf2 * 2][0] = r0;     b[nf2 * 2][1] = r1;
                b[nf2 * 2 + 1][0] = r2; b[nf2 * 2 + 1][1] = r3;
            }
            #pragma unroll
            for (int mf = 0; mf < 2; mf++)
                #pragma unroll
                for (int nf = 0; nf < 8; nf++)
                    mma16816(acc[mf][nf], a[mf], b[nf]);
        }
        __syncthreads();
    }

    // ---- phase 1: fused = relu(text*(m1+b1) + (m2+b2)) -> SF; export 8 halo cols ----
    float* SF = (float*)smem;                  // [128][SF_STRIDE], e_l in [0,64)
    float* SC = SF + 128 * SF_STRIDE;          // [128][SC_STRIDE]
    #pragma unroll
    for (int mf = 0; mf < 2; mf++) {
        int ml_a = mw * 32 + mf * 16 + (lane >> 2);
        int ml_b = ml_a + 8;
        int m_a = m0 + ml_a, m_b = m0 + ml_b;
        const float* trow_a = text + (size_t)(m_a / VV) * DD;
        const float* trow_b = text + (size_t)(m_b / VV) * DD;
        #pragma unroll
        for (int nf = 0; nf < 8; nf++) {
            int e_l = nw * 32 + nf * 4 + (lane & 3);
            int e_g = eb * 64 + e_l;
            float bb1 = __ldg(b1 + e_g), bb2 = __ldg(b2 + e_g);
            float va = fmaxf(fmaf(__ldg(trow_a + e_g), acc[mf][nf][0] + bb1,
                                  acc[mf][nf][1] + bb2), 0.f);
            float vb = fmaxf(fmaf(__ldg(trow_b + e_g), acc[mf][nf][2] + bb1,
                                  acc[mf][nf][3] + bb2), 0.f);
            SF[ml_a * SF_STRIDE + e_l] = va;
            SF[ml_b * SF_STRIDE + e_l] = vb;
            if (e_l < 4 || e_l >= 60) {
                int sl = (e_l < 4) ? e_l : (e_l - 56);   // slots 0-3, 4-7
                g_Halo[(size_t)m_a * (NEB * 8) + eb * 8 + sl] = va;
                g_Halo[(size_t)m_b * (NEB * 8) + eb * 8 + sl] = vb;
            }
        }
    }
    __syncthreads();

    // ---- phase 2: conv1 + relu for e_l in [1,63) -> SC[ml][e_l-1] ----
    float w10 = __ldg(cw1), w11 = __ldg(cw1 + 1), w12 = __ldg(cw1 + 2), bc1 = __ldg(cb1);
    for (int idx = tid; idx < 128 * 62; idx += 256) {
        int ml = idx / 62, j = idx - ml * 62;
        const float* F = SF + ml * SF_STRIDE + j;     // F[j] = SF[e_l-1]
        SC[ml * SC_STRIDE + j] = fmaxf(w10 * F[0] + w11 * F[1] + w12 * F[2] + bc1, 0.f);
    }
    __syncthreads();

    // ---- phase 3: conv2 for e_l in [2,62) -> out (60 interior cols) ----
    float w20 = __ldg(cw2), w21 = __ldg(cw2 + 1), w22 = __ldg(cw2 + 2), bc2 = __ldg(cb2);
    for (int idx = tid; idx < 128 * 60; idx += 256) {
        int ml = idx / 60, i = idx - ml * 60;         // e_l = i + 2; c1 idx = e_l-1-1 = i
        const float* C = SC + ml * SC_STRIDE + i;
        out[(size_t)(m0 + ml) * DD + eb * 64 + i + 2] =
            w20 * C[0] + w21 * C[1] + w22 * C[2] + bc2;
    }
}

// ---------------- kernel 4: boundary fixup (4 cols per e-block = 48 of 768) ----------------
__device__ __forceinline__ float halo_F(const float* __restrict__ H, int x) {
    if (x < 0 || x >= DD) return 0.f;
    int ebx = x >> 6, off = x & 63;
    int sl = (off < 4) ? off : (off - 56);            // valid: off<4 or off>=60
    return H[ebx * 8 + sl];
}

__global__ void __launch_bounds__(256) fixup_kernel(const float* __restrict__ cw1,
                                                    const float* __restrict__ cb1,
                                                    const float* __restrict__ cw2,
                                                    const float* __restrict__ cb2,
                                                    float* __restrict__ out) {
    int idx = blockIdx.x * 256 + threadIdx.x;
    if (idx >= MROWS * 48) return;
    int m = idx / 48, q = idx - m * 48;
    int eb = q >> 2, t = q & 3;
    int e_l = (t < 2) ? t : (t + 60);                 // {0,1,62,63}
    int e = eb * 64 + e_l;
    const float* H = g_Halo + (size_t)m * (NEB * 8);
    float w10 = __ldg(cw1), w11 = __ldg(cw1 + 1), w12 = __ldg(cw1 + 2), bc1 = __ldg(cb1);
    float w20 = __ldg(cw2), w21 = __ldg(cw2 + 1), w22 = __ldg(cw2 + 2), bc2 = __ldg(cb2);
    // F values for x in [e-2, e+2]
    float F[5];
    #pragma unroll
    for (int d = 0; d < 5; d++) F[d] = halo_F(H, e - 2 + d);
    // c1 at e-1, e, e+1 (zero outside [0,DD))
    float c1m = (e - 1 < 0)    ? 0.f : fmaxf(w10 * F[0] + w11 * F[1] + w12 * F[2] + bc1, 0.f);
    float c1c =                        fmaxf(w10 * F[1] + w11 * F[2] + w12 * F[3] + bc1, 0.f);
    float c1p = (e + 1 >= DD)  ? 0.f : fmaxf(w10 * F[2] + w11 * F[3] + w12 * F[4] + bc1, 0.f);
    out[(size_t)m * DD + e] = w20 * c1m + w21 * c1c + w22 * c1p + bc2;
}

// ---------------- launch (single stream) ----------------
extern "C" void kernel_launch(void* const* d_in, const int* in_sizes, int n_in,
                              void* d_out, int out_size) {
    const float* text = (const float*)d_in[0];
    const float* vf   = (const float*)d_in[1];
    const float* W1   = (const float*)d_in[2];
    const float* b1   = (const float*)d_in[3];
    const float* W2   = (const float*)d_in[4];
    const float* b2   = (const float*)d_in[5];
    const float* cw1  = (const float*)d_in[6];
    const float* cb1  = (const float*)d_in[7];
    const float* cw2  = (const float*)d_in[8];
    const float* cb2  = (const float*)d_in[9];
    float* out = (float*)d_out;

    cudaFuncSetAttribute(gemm_fused_kernel, cudaFuncAttributeMaxDynamicSharedMemorySize, SM_TOTAL);

    prep_w<<<(NN * DD + 255) / 256, 256>>>(W1, W2);
    softmax_rows<<<MROWS / 8, 256>>>(vf);
    gemm_fused_kernel<<<dim3(NEB, MROWS / TM), 256, SM_TOTAL>>>(
        text, b1, b2, cw1, cb1, cw2, cb2, out);
    fixup_kernel<<<(MROWS * 48 + 255) / 256, 256>>>(cw1, cb1, cw2, cb2, out);
}